// round 1
// baseline (speedup 1.0000x reference)
#include <cuda_runtime.h>

#define B_   8
#define N_   207
#define T_   12
#define C_   64
#define L_   2484
#define LPAD 2496
#define NTILE 39

// ---------------- scratch (module globals; zero-initialized) ----------------
__device__ float g_h[B_ * LPAD * C_];   // [b][l][c]
__device__ float g_q[B_ * LPAD * 8];    // [b][l][d]
__device__ float g_k[B_ * LPAD * 8];    // [b][m][d]
__device__ float g_v[B_ * LPAD * C_];   // [b][m][c]

// packed f32x2 FMA (Blackwell): d = a*b + c elementwise on 2 packed floats
__device__ __forceinline__ float2 ffma2(float2 a, float2 b, float2 c) {
    float2 d;
    asm("fma.rn.f32x2 %0, %1, %2, %3;"
        : "=l"(reinterpret_cast<unsigned long long&>(d))
        : "l"(reinterpret_cast<unsigned long long&>(a)),
          "l"(reinterpret_cast<unsigned long long&>(b)),
          "l"(reinterpret_cast<unsigned long long&>(c)));
    return d;
}

// ---------------------------------------------------------------------------
// Kernel 1: causal conv (x2) + GLU gate + q/k/v projections, fused per l-tile
// grid (NTILE, B), 256 threads, ~186KB dynamic smem (1 block/SM)
// ---------------------------------------------------------------------------
__global__ void __launch_bounds__(256, 1)
k1_conv_qkv(const float* __restrict__ X,
            const float* __restrict__ wA, const float* __restrict__ bA,
            const float* __restrict__ wB, const float* __restrict__ bB,
            const float* __restrict__ wq, const float* __restrict__ bq,
            const float* __restrict__ wk, const float* __restrict__ bk,
            const float* __restrict__ wv, const float* __restrict__ bv)
{
    extern __shared__ float smem[];
    float* wAs = smem;              // [idx=k*64+ci][c]  12288
    float* wBs = smem + 12288;      // 12288
    float* xs  = smem + 24576;      // [l][pitch 193]    12352
    float* hs  = smem + 36928;      // [c][pitch 65]     4160
    float* wvS = smem + 41088;      // [c][pitch 68]     4352
    float* wqS = smem + 45440;      // [d*64+c]          512
    float* wkS = smem + 45952;      // 512
    float* bAs = smem + 46464;      // 64
    float* bBs = smem + 46528;      // 64
    float* bvS = smem + 46592;      // 64
    float* bqS = smem + 46656;      // 8
    float* bkS = smem + 46664;      // 8   (total 46672 floats)

    const int tid = threadIdx.x;
    const int b   = blockIdx.y;
    const int l0  = blockIdx.x * 64;

    // ---- stage weights ----
    for (int e = tid; e < 12288; e += 256) {
        int c = e & 63, idxp = e >> 6;
        int k = idxp >> 6, ci = idxp & 63;
        int src = (c * 64 + ci) * 3 + k;
        wAs[e] = wA[src];
        wBs[e] = wB[src];
    }
    for (int e = tid; e < 4096; e += 256) {
        int o = e >> 6, c = e & 63;
        wvS[c * 68 + o] = wv[e];
    }
    for (int e = tid; e < 512; e += 256) { wqS[e] = wq[e]; wkS[e] = wk[e]; }
    if (tid < 64) { bAs[tid] = bA[tid]; bBs[tid] = bB[tid]; bvS[tid] = bv[tid]; }
    if (tid < 8)  { bqS[tid] = bq[tid]; bkS[tid] = bk[tid]; }

    // ---- stage conv taps: xs[l][k*64+ci] = X[b][n][t-2+k][ci] (0 if causal-clipped) ----
    for (int e = tid; e < 64 * 192; e += 256) {
        int l = e / 192, r = e - l * 192;
        int k = r >> 6, ci = r & 63;
        int gl = l0 + l;
        float v = 0.f;
        if (gl < L_) {
            int n = gl / 12, t = gl - n * 12;
            int tt = t - 2 + k;
            if (tt >= 0) v = X[((b * N_ + n) * T_ + tt) * C_ + ci];
        }
        xs[l * 193 + r] = v;
    }
    __syncthreads();

    // ---- conv GEMM: 4c x 4l register tile per thread, f32x2 packed ----
    const int cb = (tid & 15) * 4;
    const int lb = (tid >> 4) * 4;
    float2 aA[2][4], aB[2][4];
    #pragma unroll
    for (int i = 0; i < 2; i++)
        #pragma unroll
        for (int j = 0; j < 4; j++) { aA[i][j] = make_float2(0.f, 0.f); aB[i][j] = make_float2(0.f, 0.f); }

    #pragma unroll 4
    for (int p = 0; p < 192; p++) {
        float4 wa = *(const float4*)&wAs[p * 64 + cb];
        float4 wb = *(const float4*)&wBs[p * 64 + cb];
        float2 wa0 = make_float2(wa.x, wa.y), wa1 = make_float2(wa.z, wa.w);
        float2 wb0 = make_float2(wb.x, wb.y), wb1 = make_float2(wb.z, wb.w);
        #pragma unroll
        for (int j = 0; j < 4; j++) {
            float xv = xs[(lb + j) * 193 + p];
            float2 xx = make_float2(xv, xv);
            aA[0][j] = ffma2(wa0, xx, aA[0][j]);
            aA[1][j] = ffma2(wa1, xx, aA[1][j]);
            aB[0][j] = ffma2(wb0, xx, aB[0][j]);
            aB[1][j] = ffma2(wb1, xx, aB[1][j]);
        }
    }

    // ---- gate: h = (A+bA) * sigmoid(B+bB) -> hs[c][l] ----
    #pragma unroll
    for (int i2 = 0; i2 < 2; i2++) {
        int c0 = cb + i2 * 2;
        #pragma unroll
        for (int j = 0; j < 4; j++) {
            float a0 = aA[i2][j].x + bAs[c0];
            float a1 = aA[i2][j].y + bAs[c0 + 1];
            float g0 = aB[i2][j].x + bBs[c0];
            float g1 = aB[i2][j].y + bBs[c0 + 1];
            float h0 = a0 / (1.f + __expf(-g0));
            float h1 = a1 / (1.f + __expf(-g1));
            hs[c0 * 65 + lb + j]       = h0;
            hs[(c0 + 1) * 65 + lb + j] = h1;
        }
    }
    __syncthreads();

    // ---- write h to gmem as [b][l][c] (residual for epilogue) ----
    for (int e = tid; e < 4096; e += 256) {
        int l = e >> 6, c = e & 63;
        int gl = l0 + l;
        if (gl < L_) g_h[((size_t)b * LPAD + gl) * 64 + c] = hs[c * 65 + l];
    }

    // ---- v = wv @ h + bv  (4o x 4l per thread, f32x2) ----
    float2 vacc[2][4];
    #pragma unroll
    for (int i = 0; i < 2; i++)
        #pragma unroll
        for (int j = 0; j < 4; j++) vacc[i][j] = make_float2(0.f, 0.f);

    #pragma unroll 4
    for (int c = 0; c < 64; c++) {
        float4 w4 = *(const float4*)&wvS[c * 68 + cb];
        float2 w0 = make_float2(w4.x, w4.y), w1 = make_float2(w4.z, w4.w);
        #pragma unroll
        for (int j = 0; j < 4; j++) {
            float hv = hs[c * 65 + lb + j];
            float2 hh = make_float2(hv, hv);
            vacc[0][j] = ffma2(w0, hh, vacc[0][j]);
            vacc[1][j] = ffma2(w1, hh, vacc[1][j]);
        }
    }
    #pragma unroll
    for (int j = 0; j < 4; j++) {
        int gl = l0 + lb + j;
        float4 o;
        o.x = vacc[0][j].x + bvS[cb];
        o.y = vacc[0][j].y + bvS[cb + 1];
        o.z = vacc[1][j].x + bvS[cb + 2];
        o.w = vacc[1][j].y + bvS[cb + 3];
        if (gl >= L_) o = make_float4(0.f, 0.f, 0.f, 0.f);
        *(float4*)&g_v[((size_t)b * LPAD + gl) * 64 + cb] = o;
    }

    // ---- q,k: each thread one l, two d values per head tensor ----
    {
        int lq = tid & 63, dd = tid >> 6;       // dd in 0..3 -> handles d=dd and d=dd+4
        float aq0 = 0.f, aq1 = 0.f, ak0 = 0.f, ak1 = 0.f;
        const float* wq0 = &wqS[dd * 64];       const float* wq1 = &wqS[(dd + 4) * 64];
        const float* wk0 = &wkS[dd * 64];       const float* wk1 = &wkS[(dd + 4) * 64];
        #pragma unroll 4
        for (int c = 0; c < 64; c++) {
            float hv = hs[c * 65 + lq];
            aq0 += wq0[c] * hv; aq1 += wq1[c] * hv;
            ak0 += wk0[c] * hv; ak1 += wk1[c] * hv;
        }
        int gl = l0 + lq;
        float q0 = aq0 + bqS[dd], q1 = aq1 + bqS[dd + 4];
        float k0 = ak0 + bkS[dd], k1 = ak1 + bkS[dd + 4];
        if (gl >= L_) { q0 = q1 = k0 = k1 = 0.f; }
        size_t base = ((size_t)b * LPAD + gl) * 8;
        g_q[base + dd] = q0; g_q[base + dd + 4] = q1;
        g_k[base + dd] = k0; g_k[base + dd + 4] = k1;
    }
}

// ---------------------------------------------------------------------------
// Kernel 2: flash-style attention + residual epilogue
// grid (NTILE, B), 256 threads = 64 rows x 4 channel-groups, ~37KB smem
// ---------------------------------------------------------------------------
__global__ void __launch_bounds__(256)
k2_attn(const float* __restrict__ gamma, float* __restrict__ out)
{
    __shared__ float kS[64 * 8];        // [j][d]
    __shared__ float vS[64 * 64];       // [j][c]
    __shared__ float pS[64 * 65];       // [row][j], pitch 65
    __shared__ float lmS[4 * 64];       // [ty][row]
    __shared__ float psS[4 * 64];       // [ty][row]

    const int tid = threadIdx.x;
    const int tx  = tid & 63;           // query row within tile
    const int ty  = tid >> 6;           // channel group / j-quarter
    const int b   = blockIdx.y;
    const int l0  = blockIdx.x * 64;
    const int gl  = l0 + tx;
    const int ob  = ty * 16;

    float qv[8];
    {
        const float4* qp = (const float4*)&g_q[((size_t)b * LPAD + gl) * 8];
        float4 q0 = qp[0], q1 = qp[1];
        qv[0] = q0.x; qv[1] = q0.y; qv[2] = q0.z; qv[3] = q0.w;
        qv[4] = q1.x; qv[5] = q1.y; qv[6] = q1.z; qv[7] = q1.w;
    }

    float mx = -1e30f, ssum = 0.f;
    float2 acc[8];
    #pragma unroll
    for (int i = 0; i < 8; i++) acc[i] = make_float2(0.f, 0.f);

    for (int m0 = 0; m0 < L_; m0 += 64) {
        __syncthreads();   // protect smem reuse across iterations
        if (tid < 128)
            *(float4*)&kS[tid * 4] = *(const float4*)&g_k[((size_t)b * LPAD + m0) * 8 + tid * 4];
        {
            const float4* vsrc = (const float4*)&g_v[((size_t)b * LPAD + m0) * 64];
            float4* vdst = (float4*)vS;
            #pragma unroll
            for (int u = 0; u < 4; u++) vdst[u * 256 + tid] = vsrc[u * 256 + tid];
        }
        __syncthreads();

        const int mvalid = L_ - m0;

        // scores for this thread's j-quarter (computed exactly once)
        float s[16];
        float lm = -1e30f;
        #pragma unroll
        for (int jj = 0; jj < 16; jj++) {
            int j = ty * 16 + jj;
            float4 k0 = *(const float4*)&kS[j * 8];
            float4 k1 = *(const float4*)&kS[j * 8 + 4];
            float d = qv[0] * k0.x + qv[1] * k0.y + qv[2] * k0.z + qv[3] * k0.w
                    + qv[4] * k1.x + qv[5] * k1.y + qv[6] * k1.z + qv[7] * k1.w;
            if (j >= mvalid) d = -1e30f;
            s[jj] = d;
            lm = fmaxf(lm, d);
        }
        lmS[ty * 64 + tx] = lm;
        __syncthreads();

        float tmax = fmaxf(fmaxf(lmS[tx], lmS[64 + tx]), fmaxf(lmS[128 + tx], lmS[192 + tx]));
        float nmx  = fmaxf(mx, tmax);
        float corr = __expf(mx - nmx);
        mx = nmx;

        float ps = 0.f;
        #pragma unroll
        for (int jj = 0; jj < 16; jj++) {
            float p = __expf(s[jj] - nmx);
            ps += p;
            pS[tx * 65 + ty * 16 + jj] = p;
        }
        psS[ty * 64 + tx] = ps;
        ssum *= corr;
        #pragma unroll
        for (int i = 0; i < 8; i++) { acc[i].x *= corr; acc[i].y *= corr; }
        __syncthreads();

        ssum += psS[tx] + psS[64 + tx] + psS[128 + tx] + psS[192 + tx];

        // v accumulation: 16 channels per thread, f32x2 packed
        const float* prow = &pS[tx * 65];
        #pragma unroll 4
        for (int j = 0; j < 64; j++) {
            float pj = prow[j];
            float2 pp = make_float2(pj, pj);
            const float4* vr = (const float4*)&vS[j * 64 + ob];
            float4 v0 = vr[0], v1 = vr[1], v2 = vr[2], v3 = vr[3];
            acc[0] = ffma2(pp, make_float2(v0.x, v0.y), acc[0]);
            acc[1] = ffma2(pp, make_float2(v0.z, v0.w), acc[1]);
            acc[2] = ffma2(pp, make_float2(v1.x, v1.y), acc[2]);
            acc[3] = ffma2(pp, make_float2(v1.z, v1.w), acc[3]);
            acc[4] = ffma2(pp, make_float2(v2.x, v2.y), acc[4]);
            acc[5] = ffma2(pp, make_float2(v2.z, v2.w), acc[5]);
            acc[6] = ffma2(pp, make_float2(v3.x, v3.y), acc[6]);
            acc[7] = ffma2(pp, make_float2(v3.z, v3.w), acc[7]);
        }
    }

    if (gl < L_) {
        float inv = 1.f / ssum;
        float g = gamma[0];
        const float4* hsrc = (const float4*)&g_h[((size_t)b * LPAD + gl) * 64 + ob];
        float4* dst = (float4*)&out[((size_t)b * L_ + gl) * 64 + ob];
        #pragma unroll
        for (int i = 0; i < 4; i++) {
            float4 h4 = hsrc[i];
            float4 o;
            o.x = g * (acc[2 * i].x     * inv) + h4.x;
            o.y = g * (acc[2 * i].y     * inv) + h4.y;
            o.z = g * (acc[2 * i + 1].x * inv) + h4.z;
            o.w = g * (acc[2 * i + 1].y * inv) + h4.w;
            dst[i] = o;
        }
    }
}

// ---------------------------------------------------------------------------
extern "C" void kernel_launch(void* const* d_in, const int* in_sizes, int n_in,
                              void* d_out, int out_size)
{
    const float* X     = (const float*)d_in[0];
    const float* wA    = (const float*)d_in[1];
    const float* bA    = (const float*)d_in[2];
    const float* wB    = (const float*)d_in[3];
    const float* bB    = (const float*)d_in[4];
    const float* wq    = (const float*)d_in[5];
    const float* bq    = (const float*)d_in[6];
    const float* wk    = (const float*)d_in[7];
    const float* bk    = (const float*)d_in[8];
    const float* wv    = (const float*)d_in[9];
    const float* bv    = (const float*)d_in[10];
    const float* gamma = (const float*)d_in[11];
    float* out = (float*)d_out;

    const size_t smem1 = 46672 * sizeof(float);   // ~186.7 KB
    cudaFuncSetAttribute(k1_conv_qkv, cudaFuncAttributeMaxDynamicSharedMemorySize, (int)smem1);

    dim3 grid(NTILE, B_);
    k1_conv_qkv<<<grid, 256, smem1>>>(X, wA, bA, wB, bB, wq, bq, wk, bk, wv, bv);
    k2_attn<<<grid, 256>>>(gamma, out);
}